// round 1
// baseline (speedup 1.0000x reference)
#include <cuda_runtime.h>
#include <cuda_bf16.h>

// Problem constants
#define B_   1024
#define L_   256
#define C_   20
#define LC_  5120   // L_*C_

// ---------------------------------------------------------------------------
// Kernel 1: out[b] = theta_0 + dot(x[b,:], theta_lc)
// ---------------------------------------------------------------------------
__global__ void lin_kernel(const float* __restrict__ x,
                           const float* __restrict__ theta0,
                           const float* __restrict__ theta_lc,
                           float* __restrict__ out) {
    int b = blockIdx.x;
    const float* xb = x + (size_t)b * LC_;
    float s = 0.0f;
    for (int j = threadIdx.x; j < LC_; j += 256)
        s += xb[j] * theta_lc[j];
    __shared__ float red[256];
    red[threadIdx.x] = s;
    __syncthreads();
    for (int o = 128; o > 0; o >>= 1) {
        if (threadIdx.x < o) red[threadIdx.x] += red[threadIdx.x + o];
        __syncthreads();
    }
    if (threadIdx.x == 0) out[b] = theta0[0] + red[0];
}

// ---------------------------------------------------------------------------
// Kernel 2: fused masked GEMM + diagonal dot.
//   quad[b] += sum_j ( sum_{k: l1(k) < l2(j)} x[b,k] * Theta[k,j] ) * x[b,j]
// Tile: BM=64 (batch) x BN=64 (j), BK=16. 256 threads, 4x4 register tile.
// K-loop truncated at l2max*C (mask kills everything beyond).
// ---------------------------------------------------------------------------
#define BM 64
#define BN 64
#define BK 16

__global__ __launch_bounds__(256)
void quad_kernel(const float* __restrict__ x,
                 const float* __restrict__ theta,  // [LC_, LC_] row-major (row = k = (l1,c1))
                 float* __restrict__ out) {
    __shared__ float Xs[BK][68];   // padded to dodge bank conflicts; 68*4B rows stay 16B-aligned
    __shared__ float Ts[BK][BN];

    const int bm0 = blockIdx.x * BM;
    const int j0  = blockIdx.y * BN;
    const int tid = threadIdx.x;
    const int tx  = tid & 15;      // 0..15 -> column group
    const int ty  = tid >> 4;      // 0..15 -> row group

    // mask: keep Theta[k,j] iff (k / C) < (j / C). Max useful k for this tile:
    const int l2max = (j0 + BN - 1) / C_;
    const int Kend  = l2max * C_;          // exclusive bound; <= 5100 < LC_

    float acc[4][4] = {};

    // loader indexing
    const int lxb = tid >> 2;            // 0..63  : batch row within tile
    const int lxk = (tid & 3) * 4;       // 0,4,8,12: k offset (float4)
    const int ltk = tid >> 4;            // 0..15  : k row
    const int ltj = (tid & 15) * 4;      // 0..60  : j offset (float4)

    for (int k0 = 0; k0 < Kend; k0 += BK) {
        // --- load X tile [BM x BK], store transposed Xs[k][b] ---
        // k0+lxk+3 <= Kend-1+15 <= 5114 < LC_, so always in-bounds.
        {
            const float4 v = *(const float4*)(x + (size_t)(bm0 + lxb) * LC_ + k0 + lxk);
            Xs[lxk + 0][lxb] = v.x;
            Xs[lxk + 1][lxb] = v.y;
            Xs[lxk + 2][lxb] = v.z;
            Xs[lxk + 3][lxb] = v.w;
        }
        // --- load Theta tile [BK x BN] with mask applied ---
        {
            const int k = k0 + ltk;
            float4 t = make_float4(0.f, 0.f, 0.f, 0.f);
            if (k < Kend) {
                t = *(const float4*)(theta + (size_t)k * LC_ + j0 + ltj);
                const int l1 = k / C_;
                const int jj = j0 + ltj;
                if (l1 >= (jj + 0) / C_) t.x = 0.f;
                if (l1 >= (jj + 1) / C_) t.y = 0.f;
                if (l1 >= (jj + 2) / C_) t.z = 0.f;
                if (l1 >= (jj + 3) / C_) t.w = 0.f;
            }
            *(float4*)&Ts[ltk][ltj] = t;
        }
        __syncthreads();

        #pragma unroll
        for (int kk = 0; kk < BK; kk++) {
            const float4 a = *(const float4*)&Xs[kk][ty * 4];
            const float4 t = *(const float4*)&Ts[kk][tx * 4];
            acc[0][0] += a.x * t.x; acc[0][1] += a.x * t.y; acc[0][2] += a.x * t.z; acc[0][3] += a.x * t.w;
            acc[1][0] += a.y * t.x; acc[1][1] += a.y * t.y; acc[1][2] += a.y * t.z; acc[1][3] += a.y * t.w;
            acc[2][0] += a.z * t.x; acc[2][1] += a.z * t.y; acc[2][2] += a.z * t.z; acc[2][3] += a.z * t.w;
            acc[3][0] += a.w * t.x; acc[3][1] += a.w * t.y; acc[3][2] += a.w * t.z; acc[3][3] += a.w * t.w;
        }
        __syncthreads();
    }

    // --- epilogue: p[r] = sum_c acc[r][c] * x[b_r, j_c]; reduce across tx; atomicAdd ---
    float p[4];
    #pragma unroll
    for (int r = 0; r < 4; r++) {
        const int b = bm0 + ty * 4 + r;
        const float4 xj = *(const float4*)(x + (size_t)b * LC_ + j0 + tx * 4);
        p[r] = acc[r][0] * xj.x + acc[r][1] * xj.y + acc[r][2] * xj.z + acc[r][3] * xj.w;
    }
    #pragma unroll
    for (int off = 8; off > 0; off >>= 1) {
        #pragma unroll
        for (int r = 0; r < 4; r++)
            p[r] += __shfl_down_sync(0xffffffffu, p[r], off, 16);
    }
    if (tx == 0) {
        #pragma unroll
        for (int r = 0; r < 4; r++)
            atomicAdd(out + bm0 + ty * 4 + r, p[r]);
    }
}

// ---------------------------------------------------------------------------
extern "C" void kernel_launch(void* const* d_in, const int* in_sizes, int n_in,
                              void* d_out, int out_size) {
    const float* x_lc       = (const float*)d_in[0];   // [1024, 5120]
    const float* theta_0    = (const float*)d_in[1];   // [1]
    const float* theta_lc   = (const float*)d_in[2];   // [5120]
    const float* theta_lclc = (const float*)d_in[3];   // [5120, 5120]
    float* out = (float*)d_out;                        // [1024]

    // Kernel 1 writes out[b] (covers the 0xAA poison), kernel 2 accumulates.
    lin_kernel<<<B_, 256>>>(x_lc, theta_0, theta_lc, out);

    dim3 grid(B_ / BM, LC_ / BN);   // 16 x 80
    quad_kernel<<<grid, 256>>>(x_lc, theta_lclc, out);
}

// round 2
// speedup vs baseline: 1.0011x; 1.0011x over previous
#include <cuda_runtime.h>
#include <cuda_bf16.h>

// Problem constants
#define B_   1024
#define L_   256
#define C_   20
#define LC_  5120   // L_*C_

// ---------------------------------------------------------------------------
// Kernel 1: out[b] = theta_0 + dot(x[b,:], theta_lc)
// ---------------------------------------------------------------------------
__global__ void lin_kernel(const float* __restrict__ x,
                           const float* __restrict__ theta0,
                           const float* __restrict__ theta_lc,
                           float* __restrict__ out) {
    int b = blockIdx.x;
    const float* xb = x + (size_t)b * LC_;
    float s = 0.0f;
    for (int j = threadIdx.x; j < LC_; j += 256)
        s += xb[j] * theta_lc[j];
    __shared__ float red[256];
    red[threadIdx.x] = s;
    __syncthreads();
    for (int o = 128; o > 0; o >>= 1) {
        if (threadIdx.x < o) red[threadIdx.x] += red[threadIdx.x + o];
        __syncthreads();
    }
    if (threadIdx.x == 0) out[b] = theta0[0] + red[0];
}

// ---------------------------------------------------------------------------
// Kernel 2: fused masked GEMM + diagonal dot.
//   quad[b] += sum_j ( sum_{k: l1(k) < l2(j)} x[b,k] * Theta[k,j] ) * x[b,j]
// Tile: BM=64 (batch) x BN=64 (j), BK=16. 256 threads, 4x4 register tile.
// K-loop truncated at l2max*C (mask kills everything beyond).
// ---------------------------------------------------------------------------
#define BM 64
#define BN 64
#define BK 16

__global__ __launch_bounds__(256)
void quad_kernel(const float* __restrict__ x,
                 const float* __restrict__ theta,  // [LC_, LC_] row-major (row = k = (l1,c1))
                 float* __restrict__ out) {
    __shared__ float Xs[BK][68];   // padded to dodge bank conflicts; 68*4B rows stay 16B-aligned
    __shared__ float Ts[BK][BN];

    const int bm0 = blockIdx.x * BM;
    const int j0  = blockIdx.y * BN;
    const int tid = threadIdx.x;
    const int tx  = tid & 15;      // 0..15 -> column group
    const int ty  = tid >> 4;      // 0..15 -> row group

    // mask: keep Theta[k,j] iff (k / C) < (j / C). Max useful k for this tile:
    const int l2max = (j0 + BN - 1) / C_;
    const int Kend  = l2max * C_;          // exclusive bound; <= 5100 < LC_

    float acc[4][4] = {};

    // loader indexing
    const int lxb = tid >> 2;            // 0..63  : batch row within tile
    const int lxk = (tid & 3) * 4;       // 0,4,8,12: k offset (float4)
    const int ltk = tid >> 4;            // 0..15  : k row
    const int ltj = (tid & 15) * 4;      // 0..60  : j offset (float4)

    for (int k0 = 0; k0 < Kend; k0 += BK) {
        // --- load X tile [BM x BK], store transposed Xs[k][b] ---
        // k0+lxk+3 <= Kend-1+15 <= 5114 < LC_, so always in-bounds.
        {
            const float4 v = *(const float4*)(x + (size_t)(bm0 + lxb) * LC_ + k0 + lxk);
            Xs[lxk + 0][lxb] = v.x;
            Xs[lxk + 1][lxb] = v.y;
            Xs[lxk + 2][lxb] = v.z;
            Xs[lxk + 3][lxb] = v.w;
        }
        // --- load Theta tile [BK x BN] with mask applied ---
        {
            const int k = k0 + ltk;
            float4 t = make_float4(0.f, 0.f, 0.f, 0.f);
            if (k < Kend) {
                t = *(const float4*)(theta + (size_t)k * LC_ + j0 + ltj);
                const int l1 = k / C_;
                const int jj = j0 + ltj;
                if (l1 >= (jj + 0) / C_) t.x = 0.f;
                if (l1 >= (jj + 1) / C_) t.y = 0.f;
                if (l1 >= (jj + 2) / C_) t.z = 0.f;
                if (l1 >= (jj + 3) / C_) t.w = 0.f;
            }
            *(float4*)&Ts[ltk][ltj] = t;
        }
        __syncthreads();

        #pragma unroll
        for (int kk = 0; kk < BK; kk++) {
            const float4 a = *(const float4*)&Xs[kk][ty * 4];
            const float4 t = *(const float4*)&Ts[kk][tx * 4];
            acc[0][0] += a.x * t.x; acc[0][1] += a.x * t.y; acc[0][2] += a.x * t.z; acc[0][3] += a.x * t.w;
            acc[1][0] += a.y * t.x; acc[1][1] += a.y * t.y; acc[1][2] += a.y * t.z; acc[1][3] += a.y * t.w;
            acc[2][0] += a.z * t.x; acc[2][1] += a.z * t.y; acc[2][2] += a.z * t.z; acc[2][3] += a.z * t.w;
            acc[3][0] += a.w * t.x; acc[3][1] += a.w * t.y; acc[3][2] += a.w * t.z; acc[3][3] += a.w * t.w;
        }
        __syncthreads();
    }

    // --- epilogue: p[r] = sum_c acc[r][c] * x[b_r, j_c]; reduce across tx; atomicAdd ---
    float p[4];
    #pragma unroll
    for (int r = 0; r < 4; r++) {
        const int b = bm0 + ty * 4 + r;
        const float4 xj = *(const float4*)(x + (size_t)b * LC_ + j0 + tx * 4);
        p[r] = acc[r][0] * xj.x + acc[r][1] * xj.y + acc[r][2] * xj.z + acc[r][3] * xj.w;
    }
    #pragma unroll
    for (int off = 8; off > 0; off >>= 1) {
        #pragma unroll
        for (int r = 0; r < 4; r++)
            p[r] += __shfl_down_sync(0xffffffffu, p[r], off, 16);
    }
    if (tx == 0) {
        #pragma unroll
        for (int r = 0; r < 4; r++)
            atomicAdd(out + bm0 + ty * 4 + r, p[r]);
    }
}

// ---------------------------------------------------------------------------
extern "C" void kernel_launch(void* const* d_in, const int* in_sizes, int n_in,
                              void* d_out, int out_size) {
    const float* x_lc       = (const float*)d_in[0];   // [1024, 5120]
    const float* theta_0    = (const float*)d_in[1];   // [1]
    const float* theta_lc   = (const float*)d_in[2];   // [5120]
    const float* theta_lclc = (const float*)d_in[3];   // [5120, 5120]
    float* out = (float*)d_out;                        // [1024]

    // Kernel 1 writes out[b] (covers the 0xAA poison), kernel 2 accumulates.
    lin_kernel<<<B_, 256>>>(x_lc, theta_0, theta_lc, out);

    dim3 grid(B_ / BM, LC_ / BN);   // 16 x 80
    quad_kernel<<<grid, 256>>>(x_lc, theta_lclc, out);
}

// round 4
// speedup vs baseline: 5.7199x; 5.7138x over previous
#include <cuda_runtime.h>
#include <cuda_fp16.h>
#include <cstdint>

#define B_   1024
#define L_   256
#define C_   20
#define LC_  5120

#define TM   128
#define TN   128
#define NMT  8      // 1024/128
#define NNT  40     // 5120/128
#define NKT  80     // 64-wide k sub-tiles
#define TILE_BYTES 16384

// fp16 SW128-swizzled operand tiles in device scratch
__device__ __align__(256) unsigned char g_x [NMT * NKT * TILE_BYTES];   // ~10.5 MB
__device__ __align__(256) unsigned char g_th[NNT * NKT * TILE_BYTES];   // ~52.4 MB

__device__ __forceinline__ uint32_t smem_u32(const void* p) {
    uint32_t a;
    asm("{ .reg .u64 t; cvta.to.shared.u64 t, %1; cvt.u32.u64 %0, t; }" : "=r"(a) : "l"(p));
    return a;
}
__device__ __forceinline__ void cp16(uint32_t d, const unsigned char* s) {
    asm volatile("cp.async.cg.shared.global [%0], [%1], 16;" :: "r"(d), "l"(s) : "memory");
}
#define CP_COMMIT() asm volatile("cp.async.commit_group;" ::: "memory")
#define CP_WAIT(n)  asm volatile("cp.async.wait_group %0;" :: "n"(n) : "memory")

__device__ __forceinline__ void ldsm4(uint32_t* r, uint32_t addr) {
    asm volatile("ldmatrix.sync.aligned.m8n8.x4.shared.b16 {%0,%1,%2,%3}, [%4];"
        : "=r"(r[0]), "=r"(r[1]), "=r"(r[2]), "=r"(r[3]) : "r"(addr));
}
__device__ __forceinline__ void mma16816(float* d, const uint32_t* a, const uint32_t* b) {
    asm volatile("mma.sync.aligned.m16n8k16.row.col.f32.f16.f16.f32 "
        "{%0,%1,%2,%3}, {%4,%5,%6,%7}, {%8,%9}, {%0,%1,%2,%3};"
        : "+f"(d[0]), "+f"(d[1]), "+f"(d[2]), "+f"(d[3])
        : "r"(a[0]), "r"(a[1]), "r"(a[2]), "r"(a[3]), "r"(b[0]), "r"(b[1]));
}

// --- prep: x -> fp16 SW128 tiles [mt][kt][128b x 64k] ---
__global__ __launch_bounds__(256)
void prep_x_kernel(const float* __restrict__ x) {
    const int mt = blockIdx.x, kt = blockIdx.y;
    const float* src = x + (size_t)(mt * TM) * LC_ + kt * 64;
    unsigned char* dst = g_x + (size_t)(mt * NKT + kt) * TILE_BYTES;
    for (int q = threadIdx.x; q < 1024; q += 256) {
        const int r = q >> 3, c0 = (q & 7) << 3;
        const float4 v0 = *(const float4*)(src + (size_t)r * LC_ + c0);
        const float4 v1 = *(const float4*)(src + (size_t)r * LC_ + c0 + 4);
        union { __half2 h2[4]; uint4 u; } pk;
        pk.h2[0] = __floats2half2_rn(v0.x, v0.y);
        pk.h2[1] = __floats2half2_rn(v0.z, v0.w);
        pk.h2[2] = __floats2half2_rn(v1.x, v1.y);
        pk.h2[3] = __floats2half2_rn(v1.z, v1.w);
        uint32_t off = (uint32_t)(r * 128 + c0 * 2);
        off ^= (off >> 3) & 0x70u;
        *(uint4*)(dst + off) = pk.u;
    }
}

// --- prep: masked Theta^T -> fp16 SW128 tiles [nt][kt][128j x 64k] ---
__global__ __launch_bounds__(256)
void prep_theta_kernel(const float* __restrict__ th) {
    __shared__ float ts[64][129];
    const int nt = blockIdx.x, kt = blockIdx.y;
    const int j0 = nt * TN, k0 = kt * 64;
    for (int e = threadIdx.x; e < 64 * 128; e += 256) {
        const int rk = e >> 7, jj = e & 127;
        ts[rk][jj] = th[(size_t)(k0 + rk) * LC_ + j0 + jj];
    }
    __syncthreads();
    unsigned char* dst = g_th + (size_t)(nt * NKT + kt) * TILE_BYTES;
    for (int q = threadIdx.x; q < 1024; q += 256) {
        const int r = q >> 3, c0 = (q & 7) << 3;    // r = j_local, c0 = k_local
        const int l2 = (j0 + r) / C_;
        union { __half h[8]; uint4 u; } pk;
        #pragma unroll
        for (int i = 0; i < 8; i++) {
            const int l1 = (k0 + c0 + i) / C_;
            pk.h[i] = __float2half_rn((l1 < l2) ? ts[c0 + i][r] : 0.0f);
        }
        uint32_t off = (uint32_t)(r * 128 + c0 * 2);
        off ^= (off >> 3) & 0x70u;
        *(uint4*)(dst + off) = pk.u;
    }
}

// --- lin: out[b] = theta0 + dot(x[b], theta_lc) ---
__global__ void lin_kernel(const float* __restrict__ x,
                           const float* __restrict__ theta0,
                           const float* __restrict__ theta_lc,
                           float* __restrict__ out) {
    int b = blockIdx.x;
    const float* xb = x + (size_t)b * LC_;
    float s = 0.0f;
    for (int j = threadIdx.x; j < LC_; j += 256)
        s += xb[j] * theta_lc[j];
    __shared__ float red[256];
    red[threadIdx.x] = s;
    __syncthreads();
    for (int o = 128; o > 0; o >>= 1) {
        if (threadIdx.x < o) red[threadIdx.x] += red[threadIdx.x + o];
        __syncthreads();
    }
    if (threadIdx.x == 0) out[b] = theta0[0] + red[0];
}

// --- HMMA fused GEMM + diagonal dot ---
// CTA: 128(b) x 128(j); 8 warps in 2(M) x 4(N); BK=64 per chunk, double buffered.
__global__ __launch_bounds__(256, 2)
void gemm_kernel(const float* __restrict__ x, float* __restrict__ out) {
    extern __shared__ unsigned char dynsm[];
    const uint32_t smem = (smem_u32(dynsm) + 1023u) & ~1023u;

    const int tid = threadIdx.x;
    const int w = tid >> 5, l = tid & 31;
    const int wm = w >> 2, wn = w & 3;
    const int mt = blockIdx.x;
    const int nt = (int)gridDim.y - 1 - (int)blockIdx.y;   // heavy tiles first
    const int j0 = nt * TN;
    const int Kend = ((j0 + TN - 1) / C_) * C_;
    const int n = (Kend + 63) / 64;     // tail tile masked to zero in prep -> exact

    const unsigned char* aSrc = g_x  + (size_t)(mt * NKT) * TILE_BYTES;
    const unsigned char* bSrc = g_th + (size_t)(nt * NKT) * TILE_BYTES;

    float acc[4][4][4] = {};

    // ldmatrix address components (SW128: chunk xor with row&7 == l&7)
    const int rowA = wm * 64 + (l & 15);                  // + mi*16
    const int rowB = wn * 32 + (l & 7) + ((l >> 4) << 3); // + np*16
    const int aK = l >> 4;         // 0/1
    const int bK = (l >> 3) & 1;   // 0/1
    const int xs = l & 7;

    // prefetch chunk 0 -> stage 0
    {
        const uint32_t dst = smem;
        #pragma unroll
        for (int i = 0; i < 4; i++) {
            cp16(dst + (uint32_t)(i * 4096 + tid * 16), aSrc + i * 4096 + tid * 16);
            cp16(dst + 16384u + (uint32_t)(i * 4096 + tid * 16), bSrc + i * 4096 + tid * 16);
        }
        CP_COMMIT();
    }

    for (int c = 0; c < n; c++) {
        if (c + 1 < n) {
            const uint32_t dst = smem + (uint32_t)((c + 1) & 1) * 32768u;
            const unsigned char* a = aSrc + (size_t)(c + 1) * TILE_BYTES;
            const unsigned char* b = bSrc + (size_t)(c + 1) * TILE_BYTES;
            #pragma unroll
            for (int i = 0; i < 4; i++) {
                cp16(dst + (uint32_t)(i * 4096 + tid * 16), a + i * 4096 + tid * 16);
                cp16(dst + 16384u + (uint32_t)(i * 4096 + tid * 16), b + i * 4096 + tid * 16);
            }
            CP_COMMIT();
            CP_WAIT(1);
        } else {
            CP_WAIT(0);
        }
        __syncthreads();

        const uint32_t tA = smem + (uint32_t)(c & 1) * 32768u;
        const uint32_t tB = tA + 16384u;
        #pragma unroll
        for (int ks = 0; ks < 4; ks++) {
            uint32_t afr[4][4], bfr[2][4];
            #pragma unroll
            for (int mi = 0; mi < 4; mi++)
                ldsm4(afr[mi], tA + (uint32_t)((rowA + mi * 16) * 128)
                               + (uint32_t)(((ks * 2 + aK) ^ xs) << 4));
            #pragma unroll
            for (int np = 0; np < 2; np++)
                ldsm4(bfr[np], tB + (uint32_t)((rowB + np * 16) * 128)
                               + (uint32_t)(((ks * 2 + bK) ^ xs) << 4));
            #pragma unroll
            for (int mi = 0; mi < 4; mi++) {
                mma16816(acc[mi][0], afr[mi], &bfr[0][0]);
                mma16816(acc[mi][1], afr[mi], &bfr[0][2]);
                mma16816(acc[mi][2], afr[mi], &bfr[1][0]);
                mma16816(acc[mi][3], afr[mi], &bfr[1][2]);
            }
        }
        __syncthreads();
    }

    // epilogue: out[b] += sum_j D[b,j] * x[b, j0+j]
    const int q = l >> 2, ql = l & 3;
    #pragma unroll
    for (int mi = 0; mi < 4; mi++) {
        #pragma unroll
        for (int h = 0; h < 2; h++) {
            const int b = mt * TM + wm * 64 + mi * 16 + q + h * 8;
            const float* xr = x + (size_t)b * LC_ + j0 + wn * 32 + ql * 2;
            float p = 0.0f;
            #pragma unroll
            for (int ni = 0; ni < 4; ni++) {
                const float2 xv = *(const float2*)(xr + ni * 8);
                p += acc[mi][ni][h * 2 + 0] * xv.x + acc[mi][ni][h * 2 + 1] * xv.y;
            }
            p += __shfl_xor_sync(0xffffffffu, p, 1);
            p += __shfl_xor_sync(0xffffffffu, p, 2);
            if (ql == 0) atomicAdd(out + b, p);
        }
    }
}

extern "C" void kernel_launch(void* const* d_in, const int* in_sizes, int n_in,
                              void* d_out, int out_size) {
    const float* x_lc       = (const float*)d_in[0];
    const float* theta_0    = (const float*)d_in[1];
    const float* theta_lc   = (const float*)d_in[2];
    const float* theta_lclc = (const float*)d_in[3];
    float* out = (float*)d_out;

    cudaFuncSetAttribute(gemm_kernel,
                         cudaFuncAttributeMaxDynamicSharedMemorySize, 66560);

    prep_x_kernel<<<dim3(NMT, NKT), 256>>>(x_lc);
    prep_theta_kernel<<<dim3(NNT, NKT), 256>>>(theta_lclc);
    lin_kernel<<<B_, 256>>>(x_lc, theta_0, theta_lc, out);
    gemm_kernel<<<dim3(NMT, NNT), 256, 66560>>>(x_lc, out);
}

// round 5
// speedup vs baseline: 7.0536x; 1.2332x over previous
#include <cuda_runtime.h>
#include <cuda_fp16.h>
#include <cstdint>

#define B_   1024
#define L_   256
#define C_   20
#define LC_  5120

#define TM   128
#define TN   128
#define NMT  8      // 1024/128
#define NNT  40     // 5120/128
#define NKT  80     // 64-wide k sub-tiles
#define TILE_BYTES 16384
#define KS   8      // K-chunks per CTA (z-split)
#define NZ   10     // ceil(80/KS)

// fp16 SW128-swizzled operand tiles in device scratch
__device__ __align__(256) unsigned char g_x [NMT * NKT * TILE_BYTES];   // ~10.5 MB
__device__ __align__(256) unsigned char g_th[NNT * NKT * TILE_BYTES];   // ~52.4 MB

__device__ __forceinline__ uint32_t smem_u32(const void* p) {
    uint32_t a;
    asm("{ .reg .u64 t; cvta.to.shared.u64 t, %1; cvt.u32.u64 %0, t; }" : "=r"(a) : "l"(p));
    return a;
}
__device__ __forceinline__ void cp16(uint32_t d, const unsigned char* s) {
    asm volatile("cp.async.cg.shared.global [%0], [%1], 16;" :: "r"(d), "l"(s) : "memory");
}
#define CP_COMMIT() asm volatile("cp.async.commit_group;" ::: "memory")
#define CP_WAIT(n)  asm volatile("cp.async.wait_group %0;" :: "n"(n) : "memory")

__device__ __forceinline__ void ldsm4(uint32_t* r, uint32_t addr) {
    asm volatile("ldmatrix.sync.aligned.m8n8.x4.shared.b16 {%0,%1,%2,%3}, [%4];"
        : "=r"(r[0]), "=r"(r[1]), "=r"(r[2]), "=r"(r[3]) : "r"(addr));
}
__device__ __forceinline__ void mma16816(float* d, const uint32_t* a, const uint32_t* b) {
    asm volatile("mma.sync.aligned.m16n8k16.row.col.f32.f16.f16.f32 "
        "{%0,%1,%2,%3}, {%4,%5,%6,%7}, {%8,%9}, {%0,%1,%2,%3};"
        : "+f"(d[0]), "+f"(d[1]), "+f"(d[2]), "+f"(d[3])
        : "r"(a[0]), "r"(a[1]), "r"(a[2]), "r"(a[3]), "r"(b[0]), "r"(b[1]));
}

// --- prep: x -> fp16 SW128 tiles [mt][kt][128b x 64k] ---
__global__ __launch_bounds__(256)
void prep_x_kernel(const float* __restrict__ x) {
    const int mt = blockIdx.x, kt = blockIdx.y;
    const float* src = x + (size_t)(mt * TM) * LC_ + kt * 64;
    unsigned char* dst = g_x + (size_t)(mt * NKT + kt) * TILE_BYTES;
    for (int q = threadIdx.x; q < 1024; q += 256) {
        const int r = q >> 3, c0 = (q & 7) << 3;
        const float4 v0 = *(const float4*)(src + (size_t)r * LC_ + c0);
        const float4 v1 = *(const float4*)(src + (size_t)r * LC_ + c0 + 4);
        union { __half2 h2[4]; uint4 u; } pk;
        pk.h2[0] = __floats2half2_rn(v0.x, v0.y);
        pk.h2[1] = __floats2half2_rn(v0.z, v0.w);
        pk.h2[2] = __floats2half2_rn(v1.x, v1.y);
        pk.h2[3] = __floats2half2_rn(v1.z, v1.w);
        uint32_t off = (uint32_t)(r * 128 + c0 * 2);
        off ^= (off >> 3) & 0x70u;
        *(uint4*)(dst + off) = pk.u;
    }
}

// --- prep: masked Theta^T -> fp16 SW128 tiles [nt][kt][128j x 64k] ---
// Skips tiles entirely above the mask diagonal (never read by gemm).
__global__ __launch_bounds__(256)
void prep_theta_kernel(const float* __restrict__ th) {
    __shared__ float ts[64][129];
    const int nt = blockIdx.x, kt = blockIdx.y;
    const int j0 = nt * TN, k0 = kt * 64;
    const int Kend = ((j0 + TN - 1) / C_) * C_;
    if (k0 >= Kend) return;                      // fully masked -> gemm never reads it
    for (int e = threadIdx.x; e < 64 * 128; e += 256) {
        const int rk = e >> 7, jj = e & 127;
        ts[rk][jj] = th[(size_t)(k0 + rk) * LC_ + j0 + jj];
    }
    __syncthreads();
    unsigned char* dst = g_th + (size_t)(nt * NKT + kt) * TILE_BYTES;
    for (int q = threadIdx.x; q < 1024; q += 256) {
        const int r = q >> 3, c0 = (q & 7) << 3;    // r = j_local, c0 = k_local
        const int l2 = (j0 + r) / C_;
        union { __half h[8]; uint4 u; } pk;
        #pragma unroll
        for (int i = 0; i < 8; i++) {
            const int l1 = (k0 + c0 + i) / C_;
            pk.h[i] = __float2half_rn((l1 < l2) ? ts[c0 + i][r] : 0.0f);
        }
        uint32_t off = (uint32_t)(r * 128 + c0 * 2);
        off ^= (off >> 3) & 0x70u;
        *(uint4*)(dst + off) = pk.u;
    }
}

// --- lin: out[b] = theta0 + dot(x[b], theta_lc) ---
__global__ void lin_kernel(const float* __restrict__ x,
                           const float* __restrict__ theta0,
                           const float* __restrict__ theta_lc,
                           float* __restrict__ out) {
    int b = blockIdx.x;
    const float* xb = x + (size_t)b * LC_;
    float s = 0.0f;
    for (int j = threadIdx.x; j < LC_; j += 256)
        s += xb[j] * theta_lc[j];
    __shared__ float red[256];
    red[threadIdx.x] = s;
    __syncthreads();
    for (int o = 128; o > 0; o >>= 1) {
        if (threadIdx.x < o) red[threadIdx.x] += red[threadIdx.x + o];
        __syncthreads();
    }
    if (threadIdx.x == 0) out[b] = theta0[0] + red[0];
}

// --- HMMA fused GEMM + diagonal dot, K-split balanced ---
// CTA: 128(b) x 128(j) x (<=KS k-chunks of 64); 8 warps 2Mx4N; double buffered.
__global__ __launch_bounds__(256, 2)
void gemm_kernel(const float* __restrict__ x, float* __restrict__ out) {
    extern __shared__ unsigned char dynsm[];
    const uint32_t smem = (smem_u32(dynsm) + 1023u) & ~1023u;

    const int tid = threadIdx.x;
    const int w = tid >> 5, l = tid & 31;
    const int wm = w >> 2, wn = w & 3;
    const int mt = blockIdx.x;
    const int nt = (int)gridDim.y - 1 - (int)blockIdx.y;   // heavy tiles first
    const int j0 = nt * TN;
    const int Kend = ((j0 + TN - 1) / C_) * C_;
    const int n = (Kend + 63) / 64;          // total 64-wide chunks for this nt
    const int c0 = (int)blockIdx.z * KS;
    if (c0 >= n) return;                      // no work for this z-slice
    const int cEnd = min(n, c0 + KS);

    const unsigned char* aSrc = g_x  + (size_t)(mt * NKT) * TILE_BYTES;
    const unsigned char* bSrc = g_th + (size_t)(nt * NKT) * TILE_BYTES;

    float acc[4][4][4] = {};

    // ldmatrix address components (SW128: 16B-chunk index xor'd with row&7)
    const int rowA = wm * 64 + (l & 15);                  // + mi*16
    const int rowB = wn * 32 + (l & 7) + ((l >> 4) << 3); // + np*16
    const int aK = l >> 4;         // 0/1
    const int bK = (l >> 3) & 1;   // 0/1
    const int xs = l & 7;

    // prefetch chunk c0
    {
        const uint32_t dst = smem + (uint32_t)(c0 & 1) * 32768u;
        const unsigned char* a = aSrc + (size_t)c0 * TILE_BYTES;
        const unsigned char* b = bSrc + (size_t)c0 * TILE_BYTES;
        #pragma unroll
        for (int i = 0; i < 4; i++) {
            cp16(dst + (uint32_t)(i * 4096 + tid * 16), a + i * 4096 + tid * 16);
            cp16(dst + 16384u + (uint32_t)(i * 4096 + tid * 16), b + i * 4096 + tid * 16);
        }
        CP_COMMIT();
    }

    for (int c = c0; c < cEnd; c++) {
        if (c + 1 < cEnd) {
            const uint32_t dst = smem + (uint32_t)((c + 1) & 1) * 32768u;
            const unsigned char* a = aSrc + (size_t)(c + 1) * TILE_BYTES;
            const unsigned char* b = bSrc + (size_t)(c + 1) * TILE_BYTES;
            #pragma unroll
            for (int i = 0; i < 4; i++) {
                cp16(dst + (uint32_t)(i * 4096 + tid * 16), a + i * 4096 + tid * 16);
                cp16(dst + 16384u + (uint32_t)(i * 4096 + tid * 16), b + i * 4096 + tid * 16);
            }
            CP_COMMIT();
            CP_WAIT(1);
        } else {
            CP_WAIT(0);
        }
        __syncthreads();

        const uint32_t tA = smem + (uint32_t)(c & 1) * 32768u;
        const uint32_t tB = tA + 16384u;
        #pragma unroll
        for (int ks = 0; ks < 4; ks++) {
            uint32_t afr[4][4], bfr[2][4];
            #pragma unroll
            for (int mi = 0; mi < 4; mi++)
                ldsm4(afr[mi], tA + (uint32_t)((rowA + mi * 16) * 128)
                               + (uint32_t)(((ks * 2 + aK) ^ xs) << 4));
            #pragma unroll
            for (int np = 0; np < 2; np++)
                ldsm4(bfr[np], tB + (uint32_t)((rowB + np * 16) * 128)
                               + (uint32_t)(((ks * 2 + bK) ^ xs) << 4));
            #pragma unroll
            for (int mi = 0; mi < 4; mi++) {
                mma16816(acc[mi][0], afr[mi], &bfr[0][0]);
                mma16816(acc[mi][1], afr[mi], &bfr[0][2]);
                mma16816(acc[mi][2], afr[mi], &bfr[1][0]);
                mma16816(acc[mi][3], afr[mi], &bfr[1][2]);
            }
        }
        __syncthreads();
    }

    // epilogue: out[b] += sum_j Dpartial[b,j] * x[b, j0+j]
    const int q = l >> 2, ql = l & 3;
    #pragma unroll
    for (int mi = 0; mi < 4; mi++) {
        #pragma unroll
        for (int h = 0; h < 2; h++) {
            const int b = mt * TM + wm * 64 + mi * 16 + q + h * 8;
            const float* xr = x + (size_t)b * LC_ + j0 + wn * 32 + ql * 2;
            float p = 0.0f;
            #pragma unroll
            for (int ni = 0; ni < 4; ni++) {
                const float2 xv = *(const float2*)(xr + ni * 8);
                p += acc[mi][ni][h * 2 + 0] * xv.x + acc[mi][ni][h * 2 + 1] * xv.y;
            }
            p += __shfl_xor_sync(0xffffffffu, p, 1);
            p += __shfl_xor_sync(0xffffffffu, p, 2);
            if (ql == 0) atomicAdd(out + b, p);
        }
    }
}

extern "C" void kernel_launch(void* const* d_in, const int* in_sizes, int n_in,
                              void* d_out, int out_size) {
    const float* x_lc       = (const float*)d_in[0];
    const float* theta_0    = (const float*)d_in[1];
    const float* theta_lc   = (const float*)d_in[2];
    const float* theta_lclc = (const float*)d_in[3];
    float* out = (float*)d_out;

    cudaFuncSetAttribute(gemm_kernel,
                         cudaFuncAttributeMaxDynamicSharedMemorySize, 66560);

    prep_x_kernel<<<dim3(NMT, NKT), 256>>>(x_lc);
    prep_theta_kernel<<<dim3(NNT, NKT), 256>>>(theta_lclc);
    lin_kernel<<<B_, 256>>>(x_lc, theta_0, theta_lc, out);
    gemm_kernel<<<dim3(NMT, NNT, NZ), 256, 66560>>>(x_lc, out);
}

// round 6
// speedup vs baseline: 7.4272x; 1.0530x over previous
#include <cuda_runtime.h>
#include <cuda_fp16.h>
#include <cstdint>

#define B_   1024
#define L_   256
#define C_   20
#define LC_  5120

#define TM   128
#define TN   128
#define NMT  8      // 1024/128
#define NNT  40     // 5120/128
#define NKT  80     // 64-wide k sub-tiles
#define TILE_BYTES 16384
#define KS   8      // K-chunks per CTA (z-split)
#define NZ   10     // ceil(80/KS)

__device__ __align__(256) unsigned char g_x [NMT * NKT * TILE_BYTES];   // ~10.5 MB
__device__ __align__(256) unsigned char g_th[NNT * NKT * TILE_BYTES];   // ~52.4 MB

__device__ __forceinline__ uint32_t smem_u32(const void* p) {
    uint32_t a;
    asm("{ .reg .u64 t; cvta.to.shared.u64 t, %1; cvt.u32.u64 %0, t; }" : "=r"(a) : "l"(p));
    return a;
}
__device__ __forceinline__ void cp16(uint32_t d, const unsigned char* s) {
    asm volatile("cp.async.cg.shared.global [%0], [%1], 16;" :: "r"(d), "l"(s) : "memory");
}
#define CP_COMMIT() asm volatile("cp.async.commit_group;" ::: "memory")
#define CP_WAIT(n)  asm volatile("cp.async.wait_group %0;" :: "n"(n) : "memory")

__device__ __forceinline__ void ldsm4(uint32_t* r, uint32_t addr) {
    asm volatile("ldmatrix.sync.aligned.m8n8.x4.shared.b16 {%0,%1,%2,%3}, [%4];"
        : "=r"(r[0]), "=r"(r[1]), "=r"(r[2]), "=r"(r[3]) : "r"(addr));
}
__device__ __forceinline__ void mma16816(float* d, const uint32_t* a, const uint32_t* b) {
    asm volatile("mma.sync.aligned.m16n8k16.row.col.f32.f16.f16.f32 "
        "{%0,%1,%2,%3}, {%4,%5,%6,%7}, {%8,%9}, {%0,%1,%2,%3};"
        : "+f"(d[0]), "+f"(d[1]), "+f"(d[2]), "+f"(d[3])
        : "r"(a[0]), "r"(a[1]), "r"(a[2]), "r"(a[3]), "r"(b[0]), "r"(b[1]));
}

// --- init: out[b] = theta0 ---
__global__ void init_out_kernel(const float* __restrict__ theta0, float* __restrict__ out) {
    out[blockIdx.x * 256 + threadIdx.x] = theta0[0];
}

// --- prep: x -> fp16 SW128 tiles; fused lin partial: out[b] += dot(x[b,k0:k0+64], theta_lc[...]) ---
__global__ __launch_bounds__(256)
void prep_x_kernel(const float* __restrict__ x, const float* __restrict__ theta_lc,
                   float* __restrict__ out) {
    const int mt = blockIdx.x, kt = blockIdx.y;
    const float* src = x + (size_t)(mt * TM) * LC_ + kt * 64;
    const float* tl  = theta_lc + kt * 64;
    unsigned char* dst = g_x + (size_t)(mt * NKT + kt) * TILE_BYTES;
    for (int q = threadIdx.x; q < 1024; q += 256) {
        const int r = q >> 3, c0 = (q & 7) << 3;
        const float4 v0 = *(const float4*)(src + (size_t)r * LC_ + c0);
        const float4 v1 = *(const float4*)(src + (size_t)r * LC_ + c0 + 4);
        union { __half2 h2[4]; uint4 u; } pk;
        pk.h2[0] = __floats2half2_rn(v0.x, v0.y);
        pk.h2[1] = __floats2half2_rn(v0.z, v0.w);
        pk.h2[2] = __floats2half2_rn(v1.x, v1.y);
        pk.h2[3] = __floats2half2_rn(v1.z, v1.w);
        uint32_t off = (uint32_t)(r * 128 + c0 * 2);
        off ^= (off >> 3) & 0x70u;
        *(uint4*)(dst + off) = pk.u;
        // lin partial for this thread's 8 elements
        const float4 t0 = *(const float4*)(tl + c0);
        const float4 t1 = *(const float4*)(tl + c0 + 4);
        float s = v0.x * t0.x + v0.y * t0.y + v0.z * t0.z + v0.w * t0.w
                + v1.x * t1.x + v1.y * t1.y + v1.z * t1.z + v1.w * t1.w;
        s += __shfl_xor_sync(0xffffffffu, s, 1);
        s += __shfl_xor_sync(0xffffffffu, s, 2);
        s += __shfl_xor_sync(0xffffffffu, s, 4);
        if ((q & 7) == 0) atomicAdd(out + mt * TM + r, s);
    }
}

// --- prep: masked Theta^T -> fp16 SW128 tiles [nt][kt][128j x 64k] (skip fully-masked) ---
__global__ __launch_bounds__(256)
void prep_theta_kernel(const float* __restrict__ th) {
    __shared__ float ts[64][129];
    const int nt = blockIdx.x, kt = blockIdx.y;
    const int j0 = nt * TN, k0 = kt * 64;
    const int Kend = ((j0 + TN - 1) / C_) * C_;
    if (k0 >= Kend) return;
    for (int e = threadIdx.x; e < 64 * 128; e += 256) {
        const int rk = e >> 7, jj = e & 127;
        ts[rk][jj] = th[(size_t)(k0 + rk) * LC_ + j0 + jj];
    }
    __syncthreads();
    unsigned char* dst = g_th + (size_t)(nt * NKT + kt) * TILE_BYTES;
    for (int q = threadIdx.x; q < 1024; q += 256) {
        const int r = q >> 3, c0 = (q & 7) << 3;
        const int l2 = (j0 + r) / C_;
        union { __half h[8]; uint4 u; } pk;
        #pragma unroll
        for (int i = 0; i < 8; i++) {
            const int l1 = (k0 + c0 + i) / C_;
            pk.h[i] = __float2half_rn((l1 < l2) ? ts[c0 + i][r] : 0.0f);
        }
        uint32_t off = (uint32_t)(r * 128 + c0 * 2);
        off ^= (off >> 3) & 0x70u;
        *(uint4*)(dst + off) = pk.u;
    }
}

// --- HMMA fused GEMM + diagonal dot: 3-stage pipeline, 1 sync/chunk ---
__global__ __launch_bounds__(256, 2)
void gemm_kernel(const float* __restrict__ x, float* __restrict__ out) {
    extern __shared__ unsigned char dynsm[];

    const int mt = blockIdx.x;
    const int nt = (int)gridDim.y - 1 - (int)blockIdx.y;   // heavy tiles first
    const int j0 = nt * TN;
    const int Kend = ((j0 + TN - 1) / C_) * C_;
    const int n = (Kend + 63) / 64;
    const int c0 = (int)blockIdx.z * KS;
    if (c0 >= n) return;
    const int cEnd = min(n, c0 + KS);

    const uint32_t smem = (smem_u32(dynsm) + 1023u) & ~1023u;
    const int tid = threadIdx.x;
    const int w = tid >> 5, l = tid & 31;
    const int wm = w >> 2, wn = w & 3;

    const unsigned char* aSrc = g_x  + (size_t)(mt * NKT) * TILE_BYTES;
    const unsigned char* bSrc = g_th + (size_t)(nt * NKT) * TILE_BYTES;

    float acc[4][4][4] = {};

    const int rowA = wm * 64 + (l & 15);
    const int rowB = wn * 32 + (l & 7) + ((l >> 4) << 3);
    const int aK = l >> 4;
    const int bK = (l >> 3) & 1;
    const int xs = l & 7;

    // prologue: issue stages 0 and 1
    {
        #pragma unroll
        for (int i = 0; i < 4; i++) {
            cp16(smem + (uint32_t)(i * 4096 + tid * 16),
                 aSrc + (size_t)c0 * TILE_BYTES + i * 4096 + tid * 16);
            cp16(smem + 16384u + (uint32_t)(i * 4096 + tid * 16),
                 bSrc + (size_t)c0 * TILE_BYTES + i * 4096 + tid * 16);
        }
        CP_COMMIT();
        if (c0 + 1 < cEnd) {
            #pragma unroll
            for (int i = 0; i < 4; i++) {
                cp16(smem + 32768u + (uint32_t)(i * 4096 + tid * 16),
                     aSrc + (size_t)(c0 + 1) * TILE_BYTES + i * 4096 + tid * 16);
                cp16(smem + 32768u + 16384u + (uint32_t)(i * 4096 + tid * 16),
                     bSrc + (size_t)(c0 + 1) * TILE_BYTES + i * 4096 + tid * 16);
            }
            CP_COMMIT();
        }
    }

    for (int c = c0; c < cEnd; c++) {
        if (c + 1 < cEnd) { CP_WAIT(1); } else { CP_WAIT(0); }
        __syncthreads();
        if (c + 2 < cEnd) {
            const uint32_t dst = smem + (uint32_t)(((c - c0) + 2) % 3) * 32768u;
            const unsigned char* a = aSrc + (size_t)(c + 2) * TILE_BYTES;
            const unsigned char* b = bSrc + (size_t)(c + 2) * TILE_BYTES;
            #pragma unroll
            for (int i = 0; i < 4; i++) {
                cp16(dst + (uint32_t)(i * 4096 + tid * 16), a + i * 4096 + tid * 16);
                cp16(dst + 16384u + (uint32_t)(i * 4096 + tid * 16), b + i * 4096 + tid * 16);
            }
            CP_COMMIT();
        }

        const uint32_t tA = smem + (uint32_t)((c - c0) % 3) * 32768u;
        const uint32_t tB = tA + 16384u;
        #pragma unroll
        for (int ks = 0; ks < 4; ks++) {
            uint32_t afr[4][4], bfr[2][4];
            #pragma unroll
            for (int mi = 0; mi < 4; mi++)
                ldsm4(afr[mi], tA + (uint32_t)((rowA + mi * 16) * 128)
                               + (uint32_t)(((ks * 2 + aK) ^ xs) << 4));
            #pragma unroll
            for (int np = 0; np < 2; np++)
                ldsm4(bfr[np], tB + (uint32_t)((rowB + np * 16) * 128)
                               + (uint32_t)(((ks * 2 + bK) ^ xs) << 4));
            #pragma unroll
            for (int mi = 0; mi < 4; mi++) {
                mma16816(acc[mi][0], afr[mi], &bfr[0][0]);
                mma16816(acc[mi][1], afr[mi], &bfr[0][2]);
                mma16816(acc[mi][2], afr[mi], &bfr[1][0]);
                mma16816(acc[mi][3], afr[mi], &bfr[1][2]);
            }
        }
    }

    // epilogue: reduce per-b across N-warps in smem, then 128 global atomics
    __syncthreads();
    float* obuf = (float*)dynsm;
    if (tid < 128) obuf[tid] = 0.0f;
    __syncthreads();

    const int q = l >> 2, ql = l & 3;
    #pragma unroll
    for (int mi = 0; mi < 4; mi++) {
        #pragma unroll
        for (int h = 0; h < 2; h++) {
            const int bl = wm * 64 + mi * 16 + q + h * 8;      // local b in [0,128)
            const float* xr = x + (size_t)(mt * TM + bl) * LC_ + j0 + wn * 32 + ql * 2;
            float p = 0.0f;
            #pragma unroll
            for (int ni = 0; ni < 4; ni++) {
                const float2 xv = *(const float2*)(xr + ni * 8);
                p += acc[mi][ni][h * 2 + 0] * xv.x + acc[mi][ni][h * 2 + 1] * xv.y;
            }
            p += __shfl_xor_sync(0xffffffffu, p, 1);
            p += __shfl_xor_sync(0xffffffffu, p, 2);
            if (ql == 0) atomicAdd(obuf + bl, p);
        }
    }
    __syncthreads();
    if (tid < 128) atomicAdd(out + mt * TM + tid, obuf[tid]);
}

extern "C" void kernel_launch(void* const* d_in, const int* in_sizes, int n_in,
                              void* d_out, int out_size) {
    const float* x_lc       = (const float*)d_in[0];
    const float* theta_0    = (const float*)d_in[1];
    const float* theta_lc   = (const float*)d_in[2];
    const float* theta_lclc = (const float*)d_in[3];
    float* out = (float*)d_out;

    cudaFuncSetAttribute(gemm_kernel,
                         cudaFuncAttributeMaxDynamicSharedMemorySize, 99328);

    init_out_kernel<<<B_ / 256, 256>>>(theta_0, out);
    prep_theta_kernel<<<dim3(NNT, NKT), 256>>>(theta_lclc);
    prep_x_kernel<<<dim3(NMT, NKT), 256>>>(x_lc, theta_lc, out);
    gemm_kernel<<<dim3(NMT, NNT, NZ), 256, 99328>>>(x_lc, out);
}